// round 1
// baseline (speedup 1.0000x reference)
#include <cuda_runtime.h>
#include <cuda_bf16.h>
#include <math.h>
#include <stdint.h>

#define C_CH   128
#define N_PTS  32768
#define K_PWL  20
#define LATENT 8
#define HID    8

// ---------------- scratch (static device memory; no allocations) ----------------
__device__ float g_x[(size_t)C_CH * N_PTS];     // raw x MLP outputs [C][N]
__device__ float g_e[(size_t)C_CH * N_PTS];     // raw e MLP outputs [C][N]
__device__ float g_yp[C_CH * K_PWL];            // per-channel sorted/flipped breakpoint ys
__device__ unsigned int g_minbits[C_CH];
__device__ unsigned int g_maxbits[C_CH];
__device__ float g_minv[C_CH];
__device__ float g_scale[C_CH];
__device__ float g_psum[2048];
__device__ float g_psumsq[2048];
__device__ float g_mean;
__device__ float g_invstd;

// xp = linspace(0,1,20) in f32
#define XPV(k) ((float)((double)(k) / 19.0))
__constant__ float c_xp[K_PWL] = {
    XPV(0), XPV(1), XPV(2), XPV(3), XPV(4), XPV(5), XPV(6), XPV(7), XPV(8), XPV(9),
    XPV(10), XPV(11), XPV(12), XPV(13), XPV(14), XPV(15), XPV(16), XPV(17), XPV(18), XPV(19)
};

// ---------------- helpers ----------------
__device__ __forceinline__ unsigned int fenc(float f) {
    unsigned int u = __float_as_uint(f);
    return (u >> 31) ? ~u : (u | 0x80000000u);
}
__device__ __forceinline__ float fdec(unsigned int u) {
    return (u & 0x80000000u) ? __uint_as_float(u & 0x7FFFFFFFu) : __uint_as_float(~u);
}

// Fast, tight-absolute-error tanh: (e^{2x}-1)/(e^{2x}+1). abs err ~1e-7.
__device__ __forceinline__ float tanh_fast(float x) {
    x = fminf(fmaxf(x, -30.0f), 30.0f);
    float t = __expf(2.0f * x);
    return __fdividef(t - 1.0f, t + 1.0f);
}

// ---------------- K1: PWL generator (tiny) + init ----------------
__global__ void gen_pwl_kernel(const float* __restrict__ zf,
                               const float* __restrict__ Wf1, const float* __restrict__ bf1,
                               const float* __restrict__ Wf2, const float* __restrict__ bf2,
                               const void* __restrict__ dirs_raw) {
    int c = threadIdx.x;  // 128 threads, one per channel
    __shared__ int mode;  // 0 = int32, 1 = uint8/bool, 2 = float32
    if (c == 0) {
        const unsigned char* b = (const unsigned char*)dirs_raw;
        bool off_zero = true, all01 = true;
        for (int i = 0; i < 128; i++) {
            unsigned char v = b[i];
            if ((i & 3) != 0 && v != 0) off_zero = false;
            if (v > 1) all01 = false;
        }
        mode = off_zero ? 0 : (all01 ? 1 : 2);
    }
    __syncthreads();

    float z[LATENT];
#pragma unroll
    for (int i = 0; i < LATENT; i++) z[i] = zf[c * LATENT + i];

    float h[HID];
#pragma unroll
    for (int j = 0; j < HID; j++) h[j] = bf1[j];
#pragma unroll
    for (int i = 0; i < LATENT; i++)
#pragma unroll
        for (int j = 0; j < HID; j++) h[j] = fmaf(z[i], Wf1[i * HID + j], h[j]);
#pragma unroll
    for (int j = 0; j < HID; j++) h[j] = tanhf(h[j]);

    float pts[K_PWL];
#pragma unroll
    for (int k = 0; k < K_PWL; k++) {
        float s = bf2[k];
#pragma unroll
        for (int j = 0; j < HID; j++) s = fmaf(h[j], Wf2[j * K_PWL + k], s);
        pts[k] = tanhf(s);
    }
    // insertion sort ascending
    for (int a = 1; a < K_PWL; a++) {
        float v = pts[a];
        int b = a - 1;
        while (b >= 0 && pts[b] > v) { pts[b + 1] = pts[b]; b--; }
        pts[b + 1] = v;
    }
    bool dir;
    if (mode == 0)      dir = ((const int*)dirs_raw)[c] != 0;
    else if (mode == 1) dir = ((const unsigned char*)dirs_raw)[c] != 0;
    else                dir = ((const float*)dirs_raw)[c] > 0.5f;

    for (int k = 0; k < K_PWL; k++)
        g_yp[c * K_PWL + k] = dir ? pts[k] : pts[K_PWL - 1 - k];

    g_minbits[c] = 0xFFFFFFFFu;
    g_maxbits[c] = 0u;
}

// ---------------- K2: x MLP + per-channel min/max ----------------
__global__ void __launch_bounds__(256) pass_x_kernel(
    const float* __restrict__ zx,
    const float* __restrict__ W1, const float* __restrict__ b1,
    const float* __restrict__ W2, const float* __restrict__ b2) {
    float W1r[64];
#pragma unroll
    for (int i = 0; i < 64; i++) W1r[i] = __ldg(W1 + i);
    float b1r[HID], W2r[HID];
#pragma unroll
    for (int j = 0; j < HID; j++) { b1r[j] = __ldg(b1 + j); W2r[j] = __ldg(W2 + j); }
    float b2r = __ldg(b2);

    const int c = blockIdx.y;
    const int tid = threadIdx.x;
    const size_t base = (size_t)c * N_PTS;
    const int n0 = blockIdx.x * 2048;

    float lmin = 1e30f, lmax = -1e30f;
#pragma unroll
    for (int k = 0; k < 8; k++) {
        int n = n0 + k * 256 + tid;
        const float4* p = reinterpret_cast<const float4*>(zx + (base + n) * LATENT);
        float4 a = p[0], bq = p[1];
        float z[8] = {a.x, a.y, a.z, a.w, bq.x, bq.y, bq.z, bq.w};
        float h[HID];
#pragma unroll
        for (int j = 0; j < HID; j++) h[j] = b1r[j];
#pragma unroll
        for (int i = 0; i < LATENT; i++)
#pragma unroll
            for (int j = 0; j < HID; j++) h[j] = fmaf(z[i], W1r[i * HID + j], h[j]);
        float o = b2r;
#pragma unroll
        for (int j = 0; j < HID; j++) o = fmaf(tanh_fast(h[j]), W2r[j], o);
        float xv = tanh_fast(o);
        g_x[base + n] = xv;
        lmin = fminf(lmin, xv);
        lmax = fmaxf(lmax, xv);
    }

    __shared__ float red[256];
    red[tid] = lmin; __syncthreads();
    for (int s = 128; s; s >>= 1) { if (tid < s) red[tid] = fminf(red[tid], red[tid + s]); __syncthreads(); }
    if (tid == 0) atomicMin(&g_minbits[c], fenc(red[0]));
    __syncthreads();
    red[tid] = lmax; __syncthreads();
    for (int s = 128; s; s >>= 1) { if (tid < s) red[tid] = fmaxf(red[tid], red[tid + s]); __syncthreads(); }
    if (tid == 0) atomicMax(&g_maxbits[c], fenc(red[0]));
}

// ---------------- K3: e MLP + global sum / sumsq partials ----------------
__global__ void __launch_bounds__(256) pass_e_kernel(
    const float* __restrict__ ze,
    const float* __restrict__ W1, const float* __restrict__ b1,
    const float* __restrict__ W2, const float* __restrict__ b2) {
    float W1r[64];
#pragma unroll
    for (int i = 0; i < 64; i++) W1r[i] = __ldg(W1 + i);
    float b1r[HID], W2r[HID];
#pragma unroll
    for (int j = 0; j < HID; j++) { b1r[j] = __ldg(b1 + j); W2r[j] = __ldg(W2 + j); }
    float b2r = __ldg(b2);

    const int c = blockIdx.y;
    const int tid = threadIdx.x;
    const size_t base = (size_t)c * N_PTS;
    const int n0 = blockIdx.x * 2048;

    float ls = 0.0f, lq = 0.0f;
#pragma unroll
    for (int k = 0; k < 8; k++) {
        int n = n0 + k * 256 + tid;
        const float4* p = reinterpret_cast<const float4*>(ze + (base + n) * LATENT);
        float4 a = p[0], bq = p[1];
        float z[8] = {a.x, a.y, a.z, a.w, bq.x, bq.y, bq.z, bq.w};
        float h[HID];
#pragma unroll
        for (int j = 0; j < HID; j++) h[j] = b1r[j];
#pragma unroll
        for (int i = 0; i < LATENT; i++)
#pragma unroll
            for (int j = 0; j < HID; j++) h[j] = fmaf(z[i], W1r[i * HID + j], h[j]);
        float o = b2r;
#pragma unroll
        for (int j = 0; j < HID; j++) o = fmaf(tanh_fast(h[j]), W2r[j], o);
        float ev = tanh_fast(o);
        g_e[base + n] = ev;
        ls += ev;
        lq = fmaf(ev, ev, lq);
    }

    __shared__ float reds[256];
    __shared__ float redq[256];
    reds[tid] = ls; redq[tid] = lq; __syncthreads();
    for (int s = 128; s; s >>= 1) {
        if (tid < s) { reds[tid] += reds[tid + s]; redq[tid] += redq[tid + s]; }
        __syncthreads();
    }
    if (tid == 0) {
        int pid = blockIdx.y * gridDim.x + blockIdx.x;
        g_psum[pid] = reds[0];
        g_psumsq[pid] = redq[0];
    }
}

// ---------------- K4: finalize stats (deterministic double reduce) ----------------
__global__ void finalize_stats_kernel() {
    __shared__ double sd[256];
    __shared__ double sq[256];
    int tid = threadIdx.x;
    double s = 0.0, q = 0.0;
    for (int i = tid; i < 2048; i += 256) {
        s += (double)g_psum[i];
        q += (double)g_psumsq[i];
    }
    sd[tid] = s; sq[tid] = q; __syncthreads();
    for (int k = 128; k; k >>= 1) {
        if (tid < k) { sd[tid] += sd[tid + k]; sq[tid] += sq[tid + k]; }
        __syncthreads();
    }
    if (tid == 0) {
        double CN = (double)C_CH * (double)N_PTS;
        double mean = sd[0] / CN;
        double var = (sq[0] - sd[0] * sd[0] / CN) / (CN - 1.0);
        g_mean = (float)mean;
        g_invstd = (float)(1.0 / sqrt(var));
    }
    if (tid < C_CH) {
        float mn = fdec(g_minbits[tid]);
        float mx = fdec(g_maxbits[tid]);
        g_minv[tid] = mn;
        g_scale[tid] = 1.0f / (mx - mn);
    }
}

// ---------------- K5: transpose + PWL calibrate + noise ----------------
__global__ void __launch_bounds__(256) out_kernel(float* __restrict__ out) {
    __shared__ float sx[32][33];
    __shared__ float se[32][33];
    __shared__ float syp[32][21];
    __shared__ float smn[32];
    __shared__ float ssc[32];

    const int tx = threadIdx.x, ty = threadIdx.y;
    const int tid = ty * 32 + tx;
    const int n0 = blockIdx.x * 32;
    const int c0 = blockIdx.y * 32;

    for (int idx = tid; idx < 32 * K_PWL; idx += 256) {
        int cl = idx / K_PWL, k = idx % K_PWL;
        syp[cl][k] = g_yp[(c0 + cl) * K_PWL + k];
    }
    if (tid < 32) {
        smn[tid] = g_minv[c0 + tid];
        ssc[tid] = g_scale[c0 + tid];
    }
#pragma unroll
    for (int r = 0; r < 4; r++) {
        int cl = ty + r * 8;
        size_t off = (size_t)(c0 + cl) * N_PTS + n0 + tx;
        sx[cl][tx] = g_x[off];
        se[cl][tx] = g_e[off];
    }
    __syncthreads();

    const float mean = g_mean, invstd = g_invstd;
    const float mn = smn[tx], sc = ssc[tx];
#pragma unroll
    for (int r = 0; r < 4; r++) {
        int nn = ty + r * 8;
        float xv = (sx[tx][nn] - mn) * sc;
        int cnt = 0;
#pragma unroll
        for (int k = 0; k < K_PWL; k++) cnt += (c_xp[k] < xv) ? 1 : 0;
        int j = min(max(cnt - 1, 0), K_PWL - 2);
        float x0 = c_xp[j], x1 = c_xp[j + 1];
        float y0 = syp[tx][j], y1 = syp[tx][j + 1];
        float y = y0 + (xv - x0) * (y1 - y0) / (x1 - x0 + 1e-7f);
        float ev = (se[tx][nn] - mean) * invstd;
        out[(size_t)(n0 + nn) * C_CH + c0 + tx] = fmaf(0.1f, ev, y);
    }
}

// ---------------- launch ----------------
extern "C" void kernel_launch(void* const* d_in, const int* in_sizes, int n_in,
                              void* d_out, int out_size) {
    const float* zf  = (const float*)d_in[0];
    const float* zx  = (const float*)d_in[1];
    const float* ze  = (const float*)d_in[2];
    const float* Wx1 = (const float*)d_in[3];
    const float* bx1 = (const float*)d_in[4];
    const float* Wx2 = (const float*)d_in[5];
    const float* bx2 = (const float*)d_in[6];
    const float* We1 = (const float*)d_in[7];
    const float* be1 = (const float*)d_in[8];
    const float* We2 = (const float*)d_in[9];
    const float* be2 = (const float*)d_in[10];
    const float* Wf1 = (const float*)d_in[11];
    const float* bf1 = (const float*)d_in[12];
    const float* Wf2 = (const float*)d_in[13];
    const float* bf2 = (const float*)d_in[14];
    const void*  dirs = d_in[15];
    float* out = (float*)d_out;

    gen_pwl_kernel<<<1, 128>>>(zf, Wf1, bf1, Wf2, bf2, dirs);
    pass_x_kernel<<<dim3(16, 128), 256>>>(zx, Wx1, bx1, Wx2, bx2);
    pass_e_kernel<<<dim3(16, 128), 256>>>(ze, We1, be1, We2, be2);
    finalize_stats_kernel<<<1, 256>>>();
    out_kernel<<<dim3(N_PTS / 32, C_CH / 32), dim3(32, 8)>>>(out);
}